// round 15
// baseline (speedup 1.0000x reference)
#include <cuda_runtime.h>
#include <cuda_fp16.h>
#include <cstdint>

// Problem dims
#define IN_F   4096
#define OUT_F  16384
#define MROWS  2048

// GEMM tiling: BM=128, BN=128, BK=64 (fp16 -> 128B rows), 3-stage pipeline
// Warp grid 2(m) x 4(n) -> warp tile 64x32. 2 CTAs/SM, persistent tile loop.
static constexpr int BM = 128;
static constexpr int BN = 128;
static constexpr int BK = 64;
static constexpr int KITERS = IN_F / BK;                 // 64
static constexpr int A_TILE = BM * BK * 2;               // 16 KB
static constexpr int B_TILE = BN * BK * 2;               // 16 KB
static constexpr int STAGE_BYTES = A_TILE + B_TILE;      // 32 KB
static constexpr int STAGES = 3;
static constexpr int SMEM_TOTAL = STAGES * STAGE_BYTES;  // 98304 -> 2 CTAs/SM

static constexpr int NTILES = (MROWS / BM) * (OUT_F / BN);  // 2048
static constexpr int GRID   = 296;                          // 2 x 148 SMs (one wave)

// Combined prep kernel split points (x: 16 elems/thread, w: 32 elems/thread)
static constexpr int XBLOCKS = ((size_t)MROWS * IN_F) / (256 * 16);   // 2048
static constexpr int WBLOCKS = ((size_t)OUT_F * IN_F) / (256 * 32);   // 8192

// ── Scratch (device globals; no allocation) ──────────────────────────────
__device__ __half g_X16[(size_t)MROWS * IN_F];
__device__ __half g_W16[(size_t)OUT_F * IN_F];

// ── PTX helpers (sm_80-level only; family-portable) ──────────────────────
__device__ __forceinline__ uint32_t smem_u32(const void* p) {
    uint32_t a;
    asm("{ .reg .u64 t; cvta.to.shared.u64 t, %1; cvt.u32.u64 %0, t; }" : "=r"(a) : "l"(p));
    return a;
}
#define CP_ASYNC16(dst, src) \
    asm volatile("cp.async.cg.shared.global [%0], [%1], 16;" :: "r"(dst), "l"(src))
#define CP_COMMIT() asm volatile("cp.async.commit_group;" ::: "memory")
#define CP_WAIT0()  asm volatile("cp.async.wait_group 0;" ::: "memory")

__device__ __forceinline__ void ldsm4(uint32_t& r0, uint32_t& r1, uint32_t& r2, uint32_t& r3,
                                      uint32_t addr) {
    asm volatile("ldmatrix.sync.aligned.m8n8.x4.shared.b16 {%0,%1,%2,%3}, [%4];"
                 : "=r"(r0), "=r"(r1), "=r"(r2), "=r"(r3) : "r"(addr));
}
#define HMMA(c, a0, a1, a2, a3, b0, b1)                                       \
    asm volatile("mma.sync.aligned.m16n8k16.row.col.f32.f16.f16.f32 "         \
                 "{%0,%1,%2,%3},{%4,%5,%6,%7},{%8,%9},{%0,%1,%2,%3};"         \
                 : "+f"((c)[0]), "+f"((c)[1]), "+f"((c)[2]), "+f"((c)[3])     \
                 : "r"(a0), "r"(a1), "r"(a2), "r"(a3), "r"(b0), "r"(b1))

// swizzled byte offset of (row, 16B-chunk) inside a rows x 128B tile
__device__ __forceinline__ uint32_t swz(uint32_t row, uint32_t chunk) {
    return row * 128u + ((chunk ^ (row & 7u)) << 4);
}

// ── Combined prep: x fp32->fp16, W16 = ternary * fp16(scale) ─────────────
__global__ void prep_kernel(const float* __restrict__ x,
                            const int* __restrict__ tern,
                            const float* __restrict__ scales) {
    int b = blockIdx.x;
    if (b < XBLOCKS) {
        size_t i = ((size_t)b * blockDim.x + threadIdx.x) * 16;
        const float4* x4 = reinterpret_cast<const float4*>(x + i);
        float4 v4[4];
#pragma unroll
        for (int q = 0; q < 4; q++) v4[q] = x4[q];      // 4 independent 16B loads
        union { __half h[16]; uint4 u[2]; } o;
#pragma unroll
        for (int q = 0; q < 4; q++) {
            o.h[q * 4 + 0] = __float2half(v4[q].x);
            o.h[q * 4 + 1] = __float2half(v4[q].y);
            o.h[q * 4 + 2] = __float2half(v4[q].z);
            o.h[q * 4 + 3] = __float2half(v4[q].w);
        }
        uint4* dst = reinterpret_cast<uint4*>(&g_X16[i]);
        dst[0] = o.u[0];
        dst[1] = o.u[1];
    } else {
        size_t i = ((size_t)(b - XBLOCKS) * blockDim.x + threadIdx.x) * 32;
        const int4* t4 = reinterpret_cast<const int4*>(tern + i);
        int4 t[8];
#pragma unroll
        for (int q = 0; q < 8; q++) t[q] = t4[q];       // 8 independent 16B loads
        // all 32 elems lie in one 128-wide scale group (i is a multiple of 32)
        float sf = __half2float(__float2half(scales[i >> 7]));
        union { __half h[32]; uint4 u[4]; } o;
#pragma unroll
        for (int q = 0; q < 8; q++) {
            o.h[q * 4 + 0] = __float2half(sf * (float)t[q].x);  // exact: t in {-1,0,1}
            o.h[q * 4 + 1] = __float2half(sf * (float)t[q].y);
            o.h[q * 4 + 2] = __float2half(sf * (float)t[q].z);
            o.h[q * 4 + 3] = __float2half(sf * (float)t[q].w);
        }
        uint4* dst = reinterpret_cast<uint4*>(&g_W16[i]);
#pragma unroll
        for (int q = 0; q < 4; q++) dst[q] = o.u[q];
    }
}

// ── GEMM: out[M,N] = X16 @ W16^T, fp32 accum in HMMA ─────────────────────
// Persistent CTAs: each CTA streams ~7 tiles; the 3-stage cp.async pipeline
// and the register fragment double-buffer roll continuously ACROSS tile
// boundaries (issue cursor runs 2 k-iters ahead through (tile,k) space).
extern __shared__ __align__(128) char smem_raw[];

__global__ void __launch_bounds__(256, 2) qsgd_gemm(float* __restrict__ out)
{
    uint32_t sb = smem_u32(smem_raw);

    int tid = threadIdx.x, lane = tid & 31, wid = tid >> 5;
    int wm = wid & 1, wn = wid >> 1;          // warp grid 2(m) x 4(n): warp tile 64x32
    int gID = lane >> 2, tig = lane & 3;

    // ---- cp.async addressing: thread t -> row (t>>3) + 32j, chunk t&7 (bytes)
    int ld_row = tid >> 3, ld_chunk = tid & 7;
    const int8_t* baseA = reinterpret_cast<const int8_t*>(g_X16) +
                          (size_t)ld_row * (IN_F * 2) + ld_chunk * 16;
    const int8_t* baseB = reinterpret_cast<const int8_t*>(g_W16) +
                          (size_t)ld_row * (IN_F * 2) + ld_chunk * 16;
    uint32_t st0 = swz((uint32_t)ld_row, (uint32_t)ld_chunk);  // +j*4096 for row+32j

    // ---- ldmatrix per-lane address components
    uint32_t a_row_base = wm * 64 + (lane & 15);
    uint32_t a_cbit = (uint32_t)(lane >> 4);
    uint32_t b_row_base = wn * 32 + (lane & 7) + ((lane >> 4) & 1) * 8;
    uint32_t b_cbit = (uint32_t)((lane >> 3) & 1);

    float fa[4][4][4];
#pragma unroll
    for (int mt = 0; mt < 4; mt++)
#pragma unroll
        for (int nt = 0; nt < 4; nt++)
#pragma unroll
            for (int r = 0; r < 4; r++) fa[mt][nt][r] = 0.0f;

    // fragment double buffers
    uint32_t af[2][4][4];
    uint32_t bf[2][4][2];

#define LOAD_FRAGS(buf, sA_, sB_, pks)                                              \
    do {                                                                            \
        _Pragma("unroll")                                                           \
        for (int mt = 0; mt < 4; mt++) {                                            \
            uint32_t row = a_row_base + mt * 16;                                    \
            uint32_t addr = (sA_) + row * 128u +                                    \
                            (((2u * (pks) + a_cbit) ^ (row & 7u)) << 4);            \
            ldsm4(af[buf][mt][0], af[buf][mt][1], af[buf][mt][2], af[buf][mt][3],   \
                  addr);                                                            \
        }                                                                           \
        _Pragma("unroll")                                                           \
        for (int nb = 0; nb < 2; nb++) {                                            \
            uint32_t row = b_row_base + nb * 16;                                    \
            uint32_t addr = (sB_) + row * 128u +                                    \
                            (((2u * (pks) + b_cbit) ^ (row & 7u)) << 4);            \
            uint32_t r0, r1, r2, r3;                                                \
            ldsm4(r0, r1, r2, r3, addr);                                            \
            bf[buf][nb * 2 + 0][0] = r0; bf[buf][nb * 2 + 0][1] = r1;               \
            bf[buf][nb * 2 + 1][0] = r2; bf[buf][nb * 2 + 1][1] = r3;               \
        }                                                                           \
    } while (0)

    // ---- issue cursor: walks (tile_i, it_i) 2 k-iters ahead of compute
    int tile_i = blockIdx.x, it_i = 0, stage_i = 0;
    const int8_t* pA = baseA + (size_t)(tile_i & 15) * BM * (size_t)(IN_F * 2);
    const int8_t* pB = baseB + (size_t)(tile_i >> 4) * BN * (size_t)(IN_F * 2);

#define ISSUE_STEP()                                                                \
    do {                                                                            \
        if (tile_i < NTILES) {                                                      \
            uint32_t s_a = sb + stage_i * STAGE_BYTES;                              \
            _Pragma("unroll")                                                       \
            for (int j = 0; j < 4; j++) {                                           \
                size_t go = (size_t)(32 * j) * (IN_F * 2);                          \
                CP_ASYNC16(s_a + st0 + j * 4096,          pA + go);                 \
                CP_ASYNC16(s_a + A_TILE + st0 + j * 4096, pB + go);                 \
            }                                                                       \
        }                                                                           \
        CP_COMMIT();                                                                \
        stage_i = (stage_i == STAGES - 1) ? 0 : stage_i + 1;                        \
        pA += BK * 2; pB += BK * 2;                                                 \
        if (++it_i == KITERS) {                                                     \
            it_i = 0; tile_i += GRID;                                               \
            if (tile_i < NTILES) {                                                  \
                pA = baseA + (size_t)(tile_i & 15) * BM * (size_t)(IN_F * 2);       \
                pB = baseB + (size_t)(tile_i >> 4) * BN * (size_t)(IN_F * 2);       \
            }                                                                       \
        }                                                                           \
    } while (0)

    // ---- prologue: issue first two stages, then preload fragments
    ISSUE_STEP();
    ISSUE_STEP();
    CP_WAIT0();
    __syncthreads();
    int stage_c = 0;
    LOAD_FRAGS(0, sb, sb + A_TILE, 0u);

    // ---- persistent tile loop
    for (int tile_c = blockIdx.x; tile_c < NTILES; tile_c += GRID) {
        for (int it = 0; it < KITERS; it++) {
            ISSUE_STEP();   // keeps the pipeline 2 k-iters ahead (crosses tiles)

            uint32_t sA = sb + stage_c * STAGE_BYTES;
            uint32_t sB = sA + A_TILE;
            int stage_n = (stage_c == STAGES - 1) ? 0 : stage_c + 1;
            uint32_t sAn = sb + stage_n * STAGE_BYTES;   // next k-iter (may be next tile)
            uint32_t sBn = sAn + A_TILE;

            // 4 k16 steps; prefetch step j+1 (or next iter's step 0) during HMMAs of j
#pragma unroll
            for (int ks = 0; ks < 4; ks++) {
                int cur = ks & 1, nxt = cur ^ 1;
                if (ks < 3) {
                    LOAD_FRAGS(nxt, sA, sB, (uint32_t)(ks + 1));
                } else {
                    LOAD_FRAGS(nxt, sAn, sBn, 0u);   // (it+1, ks=0); dead after last tile
                }
#pragma unroll
                for (int mt = 0; mt < 4; mt++)
#pragma unroll
                    for (int nt = 0; nt < 4; nt++)
                        HMMA(fa[mt][nt], af[cur][mt][0], af[cur][mt][1],
                             af[cur][mt][2], af[cur][mt][3],
                             bf[cur][nt][0], bf[cur][nt][1]);
            }
            stage_c = stage_n;

            // retire this iter's cp.async group; frees buffer for the issue 2 ahead
            CP_WAIT0();
            __syncthreads();
        }

        // ---- epilogue for tile_c (cp.asyncs for the next tile are in flight)
        int mt0 = tile_c & 15, nt0 = tile_c >> 4;
#pragma unroll
        for (int mt = 0; mt < 4; mt++)
#pragma unroll
            for (int rr = 0; rr < 2; rr++) {
                int m_g = mt0 * BM + wm * 64 + mt * 16 + gID + rr * 8;
                float* op = out + (size_t)m_g * OUT_F + nt0 * BN + wn * 32 + tig * 2;
#pragma unroll
                for (int nt = 0; nt < 4; nt++) {
                    float2 v;
                    v.x = fa[mt][nt][rr * 2 + 0];
                    v.y = fa[mt][nt][rr * 2 + 1];
                    *reinterpret_cast<float2*>(op + nt * 8) = v;
                }
            }
        // reset accumulators for the next tile
#pragma unroll
        for (int mt = 0; mt < 4; mt++)
#pragma unroll
            for (int nt = 0; nt < 4; nt++)
#pragma unroll
                for (int r = 0; r < 4; r++) fa[mt][nt][r] = 0.0f;
    }
#undef ISSUE_STEP
#undef LOAD_FRAGS
}

// ── Host ─────────────────────────────────────────────────────────────────
extern "C" void kernel_launch(void* const* d_in, const int* in_sizes, int n_in,
                              void* d_out, int out_size) {
    const float* x      = (const float*)d_in[0];
    const int*   tern   = (const int*)d_in[1];
    const float* scales = (const float*)d_in[2];
    float* out = (float*)d_out;

    prep_kernel<<<XBLOCKS + WBLOCKS, 256>>>(x, tern, scales);

    cudaFuncSetAttribute((const void*)qsgd_gemm,
                         cudaFuncAttributeMaxDynamicSharedMemorySize, SMEM_TOTAL);
    // one persistent co-resident wave: 2 CTAs x 148 SMs
    qsgd_gemm<<<GRID, 256, SMEM_TOTAL>>>(out);
}